// round 1
// baseline (speedup 1.0000x reference)
#include <cuda_runtime.h>
#include <math.h>

#define N_NODES 8192
#define F_IN    256
#define F_OUT   256
#define THETA   0.5f
#define ALPHA_S 0.2f
#define NEG_INF -9000000000000000.0f

// ---------------- scratch (device globals, no runtime alloc) ----------------
__device__ float g_Wh[N_NODES * F_OUT];          // 8 MB
__device__ float g_f1[N_NODES];
__device__ float g_f2[N_NODES];
__device__ float g_rowsum[N_NODES];
__device__ float g_P[(size_t)N_NODES * N_NODES]; // 256 MB unnormalized softmax

// ---------------- generic tiled fp32 GEMM ----------------
// C[M,N] = A[M,K] @ B[K,N].  EPI==1: C = elu(C / rowsum[row]).
// Requires M%BM==0, N%BN==0, K%BK==0 (true for all our shapes).
template<int BM, int BN, int BK, int TM, int TN, int EPI>
__global__ void gemm_kernel(const float* __restrict__ A,
                            const float* __restrict__ B,
                            float* __restrict__ C,
                            const float* __restrict__ rowsum,
                            int M, int K, int N)
{
    __shared__ float As[BK][BM + 4];
    __shared__ float Bs[BK][BN + 4];

    const int tid  = threadIdx.x;            // 256 threads
    const int tx   = tid % (BN / TN);        // 16
    const int ty   = tid / (BN / TN);        // 16
    const int row0 = blockIdx.y * BM;
    const int col0 = blockIdx.x * BN;

    float acc[TM][TN];
    #pragma unroll
    for (int i = 0; i < TM; i++)
        #pragma unroll
        for (int j = 0; j < TN; j++) acc[i][j] = 0.0f;

    for (int k0 = 0; k0 < K; k0 += BK) {
        // load A tile (BM x BK), transposed into As[k][m]
        #pragma unroll 4
        for (int idx = tid; idx < BM * BK; idx += 256) {
            int r = idx / BK, c = idx % BK;
            As[c][r] = A[(size_t)(row0 + r) * K + (k0 + c)];
        }
        // load B tile (BK x BN)
        #pragma unroll 4
        for (int idx = tid; idx < BK * BN; idx += 256) {
            int r = idx / BN, c = idx % BN;
            Bs[r][c] = B[(size_t)(k0 + r) * N + (col0 + c)];
        }
        __syncthreads();

        #pragma unroll
        for (int kk = 0; kk < BK; kk++) {
            float a_reg[TM], b_reg[TN];
            #pragma unroll
            for (int i = 0; i < TM; i++) a_reg[i] = As[kk][ty * TM + i];
            #pragma unroll
            for (int j = 0; j < TN; j++) b_reg[j] = Bs[kk][tx * TN + j];
            #pragma unroll
            for (int i = 0; i < TM; i++)
                #pragma unroll
                for (int j = 0; j < TN; j++)
                    acc[i][j] = fmaf(a_reg[i], b_reg[j], acc[i][j]);
        }
        __syncthreads();
    }

    #pragma unroll
    for (int i = 0; i < TM; i++) {
        int r = row0 + ty * TM + i;
        float inv = 1.0f;
        if (EPI == 1) inv = 1.0f / rowsum[r];
        #pragma unroll
        for (int j = 0; j < TN; j++) {
            int c = col0 + tx * TN + j;
            float v = acc[i][j];
            if (EPI == 1) {
                v *= inv;
                v = (v > 0.0f) ? v : (expf(v) - 1.0f);   // ELU
            }
            C[(size_t)r * N + c] = v;
        }
    }
}

// ---------------- f1 = Wh@a1, f2 = Wh@a2 (one warp per row) ----------------
__global__ void f1f2_kernel(const float* __restrict__ a)
{
    int gwarp = (blockIdx.x * blockDim.x + threadIdx.x) >> 5;
    int lane  = threadIdx.x & 31;
    if (gwarp >= N_NODES) return;

    const float* wh = g_Wh + (size_t)gwarp * F_OUT;
    float s1 = 0.0f, s2 = 0.0f;
    #pragma unroll
    for (int k = lane; k < F_OUT; k += 32) {
        float v = wh[k];
        s1 = fmaf(v, a[k],         s1);
        s2 = fmaf(v, a[F_OUT + k], s2);
    }
    #pragma unroll
    for (int o = 16; o > 0; o >>= 1) {
        s1 += __shfl_xor_sync(0xffffffffu, s1, o);
        s2 += __shfl_xor_sync(0xffffffffu, s2, o);
    }
    if (lane == 0) { g_f1[gwarp] = s1; g_f2[gwarp] = s2; }
}

// ---------------- per-row masked softmax (unnormalized) ----------------
// Block = one row i. Pass 1: rowmax of masked e. Pass 2: P[i,j]=exp(e-m), rowsum.
__global__ void attn_kernel(const int* __restrict__ adj,
                            const float* __restrict__ cv)
{
    const int i   = blockIdx.x;
    const int tid = threadIdx.x;      // 256
    __shared__ float red[256];

    const float f1i  = g_f1[i];
    const float bias = THETA * cv[i];
    const int* __restrict__ arow = adj + (size_t)i * N_NODES;

    // pass 1: max
    float m = NEG_INF;
    for (int j = tid; j < N_NODES; j += 256) {
        float e = f1i + g_f2[j];
        e = (e > 0.0f) ? e : ALPHA_S * e;   // leaky_relu
        e += bias;
        float em = (arow[j] > 0) ? e : NEG_INF;
        m = fmaxf(m, em);
    }
    red[tid] = m; __syncthreads();
    #pragma unroll
    for (int s = 128; s > 0; s >>= 1) {
        if (tid < s) red[tid] = fmaxf(red[tid], red[tid + s]);
        __syncthreads();
    }
    m = red[0];
    __syncthreads();

    // pass 2: p = exp(e_masked - m); note NEG_INF - NEG_INF == 0 -> p = 1
    float sum = 0.0f;
    float* __restrict__ prow = g_P + (size_t)i * N_NODES;
    for (int j = tid; j < N_NODES; j += 256) {
        float e = f1i + g_f2[j];
        e = (e > 0.0f) ? e : ALPHA_S * e;
        e += bias;
        float em = (arow[j] > 0) ? e : NEG_INF;
        float p = expf(em - m);
        prow[j] = p;
        sum += p;
    }
    red[tid] = sum; __syncthreads();
    #pragma unroll
    for (int s = 128; s > 0; s >>= 1) {
        if (tid < s) red[tid] += red[tid + s];
        __syncthreads();
    }
    if (tid == 0) g_rowsum[i] = red[0];
}

// ---------------- launch ----------------
extern "C" void kernel_launch(void* const* d_in, const int* in_sizes, int n_in,
                              void* d_out, int out_size)
{
    const float* h   = (const float*)d_in[0];   // [8192, 256]
    const int*   adj = (const int*)  d_in[1];   // [8192, 8192]
    const float* cv  = (const float*)d_in[2];   // [8192]
    const float* W   = (const float*)d_in[3];   // [256, 256]
    const float* a   = (const float*)d_in[4];   // [512, 1]
    float* out = (float*)d_out;                 // [8192, 256]

    float *pWh, *pP, *pRS;
    cudaGetSymbolAddress((void**)&pWh, g_Wh);
    cudaGetSymbolAddress((void**)&pP,  g_P);
    cudaGetSymbolAddress((void**)&pRS, g_rowsum);

    // 1) Wh = h @ W
    {
        dim3 grid(F_OUT / 64, N_NODES / 128);
        gemm_kernel<128, 64, 32, 8, 4, 0><<<grid, 256>>>(
            h, W, pWh, nullptr, N_NODES, F_IN, F_OUT);
    }
    // 2) f1, f2
    f1f2_kernel<<<N_NODES / 8, 256>>>(a);
    // 3) masked softmax numerators + rowsums
    attn_kernel<<<N_NODES, 256>>>(adj, cv);
    // 4) out = elu((P @ Wh) / rowsum)
    {
        dim3 grid(F_OUT / 64, N_NODES / 128);
        gemm_kernel<128, 64, 32, 8, 4, 1><<<grid, 256>>>(
            pP, pWh, out, pRS, N_NODES, N_NODES, F_OUT);
    }
}

// round 3
// speedup vs baseline: 5.4060x; 5.4060x over previous
#include <cuda_runtime.h>
#include <cuda_bf16.h>
#include <cstdint>
#include <math.h>

#define NN 8192
#define FD 256
#define THETA   0.5f
#define ALPHA_S 0.2f

// ---------------- device global scratch ----------------
__device__ __nv_bfloat16 g_hhi[NN * FD];
__device__ __nv_bfloat16 g_hlo[NN * FD];
__device__ __nv_bfloat16 g_WThi[FD * FD];
__device__ __nv_bfloat16 g_WTlo[FD * FD];
__device__ __nv_bfloat16 g_WhThi[FD * NN];   // Wh^T [n][k] splits
__device__ __nv_bfloat16 g_WhTlo[FD * NN];
__device__ float g_f1[NN];
__device__ float g_f2[NN];
__device__ float g_rowsum[NN];
__device__ __nv_bfloat16 g_Phi[(size_t)NN * NN];   // 128 MB
__device__ __nv_bfloat16 g_Plo[(size_t)NN * NN];   // 128 MB

// ---------------- PTX helpers (base sm_90 feature set only) ----------------
__device__ __forceinline__ uint32_t smem_u32(const void* p) {
    uint32_t a;
    asm("{ .reg .u64 t; cvta.to.shared.u64 t, %1; cvt.u32.u64 %0, t; }"
        : "=r"(a) : "l"(p));
    return a;
}
__device__ __forceinline__ void cp_async16(uint32_t dst, const void* src) {
    asm volatile("cp.async.cg.shared.global [%0], [%1], 16;"
                 :: "r"(dst), "l"(src) : "memory");
}
__device__ __forceinline__ void cp_commit() {
    asm volatile("cp.async.commit_group;" ::: "memory");
}
template<int N>
__device__ __forceinline__ void cp_wait() {
    asm volatile("cp.async.wait_group %0;" :: "n"(N) : "memory");
}
__device__ __forceinline__ void ldm_x4(uint32_t addr, uint32_t& r0, uint32_t& r1,
                                       uint32_t& r2, uint32_t& r3) {
    asm volatile("ldmatrix.sync.aligned.m8n8.x4.shared.b16 {%0,%1,%2,%3}, [%4];"
                 : "=r"(r0), "=r"(r1), "=r"(r2), "=r"(r3) : "r"(addr));
}
__device__ __forceinline__ void mma_bf16(float* c, const uint32_t* a, const uint32_t* b) {
    asm volatile(
        "mma.sync.aligned.m16n8k16.row.col.f32.bf16.bf16.f32 "
        "{%0,%1,%2,%3}, {%4,%5,%6,%7}, {%8,%9}, {%0,%1,%2,%3};"
        : "+f"(c[0]), "+f"(c[1]), "+f"(c[2]), "+f"(c[3])
        : "r"(a[0]), "r"(a[1]), "r"(a[2]), "r"(a[3]), "r"(b[0]), "r"(b[1]));
}

// SMEM: 2 stages x 4 tiles (Ahi,Alo,Bhi,Blo), each 128 rows x 80B
static constexpr int ROWB   = 80;
static constexpr int TILE_B = 128 * ROWB;        // 10240
static constexpr int STAGE_B = 4 * TILE_B;       // 40960
static constexpr int SMEM_SZ = 2 * STAGE_B;      // 81920

// ---------------- split-bf16 mma.sync GEMM ----------------
// C[128,128] per CTA = (Ahi+Alo)[M,K] @ (Bhi+Blo)[N,K]^T, fp32 accum.
// EPI==0: write C^T bf16 hi/lo to WhT (coalesced via smem transpose).
// EPI==1: out[r][c] = elu(C / rowsum[r]), fp32 row-major.
template<int KCHUNKS, int EPI>
__global__ void __launch_bounds__(256, 1) mma_gemm(
    const __nv_bfloat16* __restrict__ Ahi, const __nv_bfloat16* __restrict__ Alo,
    const __nv_bfloat16* __restrict__ Bhi, const __nv_bfloat16* __restrict__ Blo,
    __nv_bfloat16* __restrict__ ThiOut, __nv_bfloat16* __restrict__ TloOut,
    const float* __restrict__ rowsum, float* __restrict__ out)
{
    constexpr int K = KCHUNKS * 32;
    extern __shared__ char smem[];
    const uint32_t sb = smem_u32(smem);

    const int tid  = threadIdx.x;
    const int warp = tid >> 5;
    const int lane = tid & 31;
    const int wm   = warp & 3;            // 4 m-warps: rows wm*32
    const int wn   = warp >> 2;           // 2 n-warps: cols wn*64
    const int row0 = blockIdx.x * 128;
    const int col0 = blockIdx.y * 128;

    // per-lane ldmatrix offsets
    const int a_row = lane & 15;
    const int a_kb  = (lane >> 4) * 16;
    const int b_row = ((lane >> 4) << 3) + (lane & 7);
    const int b_kb  = ((lane >> 3) & 1) * 16;

    // gmem load mapping: 2 chunks per tile per thread
    const int lrow = tid >> 2;            // 0..63 (+64 on 2nd iter)
    const int lch  = tid & 3;

    float acc[2][8][4];
    #pragma unroll
    for (int i = 0; i < 2; i++)
        #pragma unroll
        for (int j = 0; j < 8; j++)
            #pragma unroll
            for (int q = 0; q < 4; q++) acc[i][j][q] = 0.0f;

    auto load_stage = [&](int s, int kc) {
        const uint32_t base = sb + s * STAGE_B;
        const int k0 = kc * 32;
        #pragma unroll
        for (int it = 0; it < 2; it++) {
            int r = lrow + it * 64;
            uint32_t doff = r * ROWB + lch * 16;
            size_t ga = (size_t)(row0 + r) * K + k0 + lch * 8;
            size_t gb = (size_t)(col0 + r) * K + k0 + lch * 8;
            cp_async16(base + 0 * TILE_B + doff, Ahi + ga);
            cp_async16(base + 1 * TILE_B + doff, Alo + ga);
            cp_async16(base + 2 * TILE_B + doff, Bhi + gb);
            cp_async16(base + 3 * TILE_B + doff, Blo + gb);
        }
        cp_commit();
    };

    load_stage(0, 0);

    for (int c = 0; c < KCHUNKS; c++) {
        const int s = c & 1;
        if (c + 1 < KCHUNKS) { load_stage(s ^ 1, c + 1); cp_wait<1>(); }
        else                 { cp_wait<0>(); }
        __syncthreads();

        const uint32_t base = sb + s * STAGE_B;
        #pragma unroll
        for (int ks = 0; ks < 2; ks++) {
            const int kb = ks * 32;
            uint32_t ah[2][4], al[2][4], bh[16], bl[16];
            #pragma unroll
            for (int mt = 0; mt < 2; mt++) {
                uint32_t ra = (wm * 32 + mt * 16 + a_row) * ROWB + kb + a_kb;
                ldm_x4(base + 0 * TILE_B + ra, ah[mt][0], ah[mt][1], ah[mt][2], ah[mt][3]);
                ldm_x4(base + 1 * TILE_B + ra, al[mt][0], al[mt][1], al[mt][2], al[mt][3]);
            }
            #pragma unroll
            for (int nb = 0; nb < 4; nb++) {
                uint32_t rb = (wn * 64 + nb * 16 + b_row) * ROWB + kb + b_kb;
                ldm_x4(base + 2 * TILE_B + rb, bh[4*nb], bh[4*nb+1], bh[4*nb+2], bh[4*nb+3]);
                ldm_x4(base + 3 * TILE_B + rb, bl[4*nb], bl[4*nb+1], bl[4*nb+2], bl[4*nb+3]);
            }
            #pragma unroll
            for (int mt = 0; mt < 2; mt++)
                #pragma unroll
                for (int nt = 0; nt < 8; nt++) {
                    mma_bf16(acc[mt][nt], ah[mt], bh + 2*nt);
                    mma_bf16(acc[mt][nt], ah[mt], bl + 2*nt);
                    mma_bf16(acc[mt][nt], al[mt], bh + 2*nt);
                }
        }
        __syncthreads();
    }

    if (EPI == 1) {
        // out = elu(C / rowsum[row]); C lane layout: c0,c1 -> (row l>>2, col 2(l&3));
        // c2,c3 -> row+8.
        #pragma unroll
        for (int mt = 0; mt < 2; mt++) {
            int rA = row0 + wm * 32 + mt * 16 + (lane >> 2);
            int rB = rA + 8;
            float invA = 1.0f / rowsum[rA];
            float invB = 1.0f / rowsum[rB];
            #pragma unroll
            for (int nt = 0; nt < 8; nt++) {
                int cc = col0 + wn * 64 + nt * 8 + (lane & 3) * 2;
                float v0 = acc[mt][nt][0] * invA;
                float v1 = acc[mt][nt][1] * invA;
                float v2 = acc[mt][nt][2] * invB;
                float v3 = acc[mt][nt][3] * invB;
                float2 oA = { v0 > 0.f ? v0 : expm1f(v0), v1 > 0.f ? v1 : expm1f(v1) };
                float2 oB = { v2 > 0.f ? v2 : expm1f(v2), v3 > 0.f ? v3 : expm1f(v3) };
                *(float2*)(out + (size_t)rA * FD + cc) = oA;
                *(float2*)(out + (size_t)rB * FD + cc) = oB;
            }
        }
    } else {
        // stage C^T bf16 hi/lo through smem, then coalesced store to [n][m]
        constexpr int TST = 272;   // 128*2B + 16B pad, 16B aligned
        __nv_bfloat16* shT = (__nv_bfloat16*)smem;                 // [128n][stride 136]
        __nv_bfloat16* slT = (__nv_bfloat16*)(smem + 128 * TST);
        #pragma unroll
        for (int mt = 0; mt < 2; mt++) {
            #pragma unroll
            for (int nt = 0; nt < 8; nt++) {
                int ml = wm * 32 + mt * 16 + (lane >> 2);
                int nl = wn * 64 + nt * 8 + (lane & 3) * 2;
                #pragma unroll
                for (int q = 0; q < 4; q++) {
                    int m = ml + (q >> 1) * 8;
                    int n = nl + (q & 1);
                    float v = acc[mt][nt][q];
                    __nv_bfloat16 hb = __float2bfloat16(v);
                    __nv_bfloat16 lb = __float2bfloat16(v - __bfloat162float(hb));
                    shT[n * 136 + m] = hb;
                    slT[n * 136 + m] = lb;
                }
            }
        }
        __syncthreads();
        #pragma unroll
        for (int it = 0; it < 8; it++) {
            int idx = tid + it * 256;        // 0..2047
            int n = idx >> 4, cm = idx & 15;
            uint4 vh = *(uint4*)(smem + n * TST + cm * 16);
            uint4 vl = *(uint4*)(smem + 128 * TST + n * TST + cm * 16);
            size_t g = (size_t)(col0 + n) * NN + row0 + cm * 8;
            *(uint4*)(ThiOut + g) = vh;
            *(uint4*)(TloOut + g) = vl;
        }
    }
}

// ---------------- input conversion: h and W^T hi/lo splits ----------------
__global__ void convert_kernel(const float* __restrict__ h, const float* __restrict__ W)
{
    int t = blockIdx.x * 256 + threadIdx.x;
    if (blockIdx.x < NN) {
        float v = h[t];
        __nv_bfloat16 hb = __float2bfloat16(v);
        g_hhi[t] = hb;
        g_hlo[t] = __float2bfloat16(v - __bfloat162float(hb));
    } else {
        int idx = t - NN * 256;
        int o = idx >> 8, i = idx & 255;
        float v = W[i * FD + o];
        __nv_bfloat16 hb = __float2bfloat16(v);
        g_WThi[idx] = hb;
        g_WTlo[idx] = __float2bfloat16(v - __bfloat162float(hb));
    }
}

// ---------------- f1/f2 from WhT splits ----------------
__global__ void f1f2_kernel(const float* __restrict__ a)
{
    int m = blockIdx.x * 256 + threadIdx.x;   // column of WhT
    float s1 = 0.0f, s2 = 0.0f;
    #pragma unroll 4
    for (int n = 0; n < FD; n++) {
        float v = __bfloat162float(g_WhThi[(size_t)n * NN + m]) +
                  __bfloat162float(g_WhTlo[(size_t)n * NN + m]);
        s1 = fmaf(v, __ldg(a + n),      s1);
        s2 = fmaf(v, __ldg(a + FD + n), s2);
    }
    g_f1[m] = s1;
    g_f2[m] = s2;
}

// ---------------- single-pass masked softmax numerators ----------------
__global__ void attn_kernel(const int* __restrict__ adj, const float* __restrict__ cv)
{
    const int i   = blockIdx.x;
    const int tid = threadIdx.x;
    __shared__ float red[256];

    const float f1i  = g_f1[i];
    const float bias = THETA * cv[i];
    const size_t base = (size_t)i * NN;

    float sum = 0.0f;
    #pragma unroll
    for (int it = 0; it < 8; it++) {
        int j = (it * 256 + tid) * 4;
        int4   av = *(const int4*)(adj + base + j);
        float4 fv = *(const float4*)(g_f2 + j);

        float p[4], e;
        e = f1i + fv.x; e = e > 0.0f ? e : ALPHA_S * e; e += bias;
        p[0] = av.x > 0 ? __expf(e) : 0.0f;
        e = f1i + fv.y; e = e > 0.0f ? e : ALPHA_S * e; e += bias;
        p[1] = av.y > 0 ? __expf(e) : 0.0f;
        e = f1i + fv.z; e = e > 0.0f ? e : ALPHA_S * e; e += bias;
        p[2] = av.z > 0 ? __expf(e) : 0.0f;
        e = f1i + fv.w; e = e > 0.0f ? e : ALPHA_S * e; e += bias;
        p[3] = av.w > 0 ? __expf(e) : 0.0f;

        sum += (p[0] + p[1]) + (p[2] + p[3]);

        __nv_bfloat16 h0 = __float2bfloat16(p[0]);
        __nv_bfloat16 h1 = __float2bfloat16(p[1]);
        __nv_bfloat16 h2 = __float2bfloat16(p[2]);
        __nv_bfloat16 h3 = __float2bfloat16(p[3]);
        __nv_bfloat162* ph = (__nv_bfloat162*)(g_Phi + base + j);
        ph[0] = __nv_bfloat162(h0, h1);
        ph[1] = __nv_bfloat162(h2, h3);
        __nv_bfloat162* pl = (__nv_bfloat162*)(g_Plo + base + j);
        pl[0] = __nv_bfloat162(__float2bfloat16(p[0] - __bfloat162float(h0)),
                               __float2bfloat16(p[1] - __bfloat162float(h1)));
        pl[1] = __nv_bfloat162(__float2bfloat16(p[2] - __bfloat162float(h2)),
                               __float2bfloat16(p[3] - __bfloat162float(h3)));
    }

    red[tid] = sum; __syncthreads();
    #pragma unroll
    for (int s = 128; s > 0; s >>= 1) {
        if (tid < s) red[tid] += red[tid + s];
        __syncthreads();
    }
    if (tid == 0) g_rowsum[i] = red[0];
}

// ---------------- launch ----------------
extern "C" void kernel_launch(void* const* d_in, const int* in_sizes, int n_in,
                              void* d_out, int out_size)
{
    const float* h   = (const float*)d_in[0];
    const int*   adj = (const int*)  d_in[1];
    const float* cv  = (const float*)d_in[2];
    const float* W   = (const float*)d_in[3];
    const float* a   = (const float*)d_in[4];
    float* out = (float*)d_out;

    __nv_bfloat16 *phhi, *phlo, *pWThi, *pWTlo, *pWhThi, *pWhTlo, *pPhi, *pPlo;
    float *prs;
    cudaGetSymbolAddress((void**)&phhi,   g_hhi);
    cudaGetSymbolAddress((void**)&phlo,   g_hlo);
    cudaGetSymbolAddress((void**)&pWThi,  g_WThi);
    cudaGetSymbolAddress((void**)&pWTlo,  g_WTlo);
    cudaGetSymbolAddress((void**)&pWhThi, g_WhThi);
    cudaGetSymbolAddress((void**)&pWhTlo, g_WhTlo);
    cudaGetSymbolAddress((void**)&pPhi,   g_Phi);
    cudaGetSymbolAddress((void**)&pPlo,   g_Plo);
    cudaGetSymbolAddress((void**)&prs,    g_rowsum);

    cudaFuncSetAttribute(mma_gemm<8, 0>,   cudaFuncAttributeMaxDynamicSharedMemorySize, SMEM_SZ);
    cudaFuncSetAttribute(mma_gemm<256, 1>, cudaFuncAttributeMaxDynamicSharedMemorySize, SMEM_SZ);

    // 1) bf16 hi/lo splits of h and W^T
    convert_kernel<<<NN + FD, 256>>>(h, W);

    // 2) Wh = h@W on mma.sync; epilogue writes WhT hi/lo
    {
        dim3 grid(NN / 128, FD / 128);
        mma_gemm<8, 0><<<grid, 256, SMEM_SZ>>>(
            phhi, phlo, pWThi, pWTlo, pWhThi, pWhTlo, nullptr, nullptr);
    }

    // 3) f1/f2
    f1f2_kernel<<<NN / 256, 256>>>(a);

    // 4) masked softmax numerators + rowsums
    attn_kernel<<<NN, 256>>>(adj, cv);

    // 5) out = elu((P @ Wh) / rowsum) on mma.sync
    {
        dim3 grid(NN / 128, FD / 128);
        mma_gemm<256, 1><<<grid, 256, SMEM_SZ>>>(
            pPhi, pPlo, pWhThi, pWhTlo, nullptr, nullptr, prs, out);
    }
}